// round 13
// baseline (speedup 1.0000x reference)
#include <cuda_runtime.h>
#include <cuda_fp16.h>
#include <math_constants.h>
#include <cstdint>
#include <cstddef>

// ---------------- Problem constants ----------------
#define BB 2
#define TT 2048
#define HH 1024
#define VV 50257
#define MTOT (BB*TT)          // 4096
#define NT 393                // ceil(50257/128) N tiles

// ---------------- GEMM tiling (fp16 operands, reg double-buffered) ----------------
#define TM 128
#define TN 128
#define NST 6                 // pipeline stages (TK=16 each)
#define NK 64                 // K iterations
#define NTHREADS 128          // 4 warps, each m64n64

#define A_U 4096              // A bytes per kt16 stage (128x16 fp16)
#define B_U 4096              // B bytes per kt16 stage (128x16 fp16)
#define ST  (A_U+B_U)         // 8192
#define SMEM_TOTAL (NST*ST)   // 49152 dynamic

// ---------------- device scratch ----------------
// A_half: [mtile 0..31][kt 0..63] tiles of 4KB; unit16B u = block(0..7)*32+lane:
//   {A[r0][c0],A[r0][c0+1]}, {A[r0+8][c0],A[r0+8][c0+1]},
//   {A[r0][c0+8],A[r0][c0+9]}, {A[r0+8][c0+8],A[r0+8][c0+9]}
//   r0 = mtile*128+block*16+(lane>>2), c0 = kt*16+(lane&3)*2
__device__ __half A_half[MTOT*HH];                     // 8 MB
// W_half: [ntile 0..392][kt 0..63] tiles of 4KB; unit16B u = pair(0..7)*32+lane:
//   ne = ntile*128+pair*16+(lane>>2), no = ne+8, c0 = kt*16+(lane&3)*2
//   {W[ne][c0..c0+1]}, {W[ne][c0+8..c0+9]}, {W[no][c0..c0+1]}, {W[no][c0+8..c0+9]}
__device__ __half W_half[(size_t)NT*131072];           // ~103 MB
__device__ float g_nll[BB*(TT-1)];
__device__ float part_m[(size_t)MTOT*NT];
__device__ float part_s[(size_t)MTOT*NT];

// ---------------- helpers ----------------
__device__ __forceinline__ unsigned pack_h2(float lo, float hi) {
    __half2 h = __floats2half2_rn(lo, hi);
    return *reinterpret_cast<unsigned*>(&h);
}
__device__ __forceinline__ void mma_f16(float* c,
    unsigned a0, unsigned a1, unsigned a2, unsigned a3,
    unsigned b0, unsigned b1)
{
    asm volatile("mma.sync.aligned.m16n8k16.row.col.f32.f16.f16.f32 "
        "{%0,%1,%2,%3}, {%4,%5,%6,%7}, {%8,%9}, {%0,%1,%2,%3};"
        : "+f"(c[0]), "+f"(c[1]), "+f"(c[2]), "+f"(c[3])
        : "r"(a0), "r"(a1), "r"(a2), "r"(a3), "r"(b0), "r"(b1));
}
__device__ __forceinline__ void cp16(void* dst, const void* src) {
    unsigned s = (unsigned)__cvta_generic_to_shared(dst);
    asm volatile("cp.async.cg.shared.global [%0], [%1], 16;" :: "r"(s), "l"(src));
}
// -inf-safe (m, s) logsumexp-state combine; fixed order -> deterministic
__device__ __forceinline__ void lse_comb(float& m, float& s, float mo, float so) {
    float M = fmaxf(m, mo);
    if (M == -CUDART_INF_F) { m = M; s = 0.f; return; }
    s = s * __expf(m - M) + so * __expf(mo - M);
    m = M;
}

// ---------------- pack kernels ----------------
__global__ void __launch_bounds__(256)
pack_A_kernel(const float* __restrict__ src)
{
    int idx  = blockIdx.x * 256 + threadIdx.x;     // 16B unit id
    int tile = idx >> 8;                            // 256 units per kt16 tile
    int v    = idx & 255;
    int mtile = tile >> 6, kt = tile & 63;
    int block = v >> 5, lane = v & 31;
    int grp = lane >> 2, tg = lane & 3;
    int r0 = mtile * 128 + block * 16 + grp;
    int c0 = kt * 16 + tg * 2;
    const float* p = src + (size_t)r0 * HH + c0;
    uint4 o;
    o.x = pack_h2(p[0],          p[1]);
    o.y = pack_h2(p[8 * HH],     p[8 * HH + 1]);
    o.z = pack_h2(p[8],          p[9]);
    o.w = pack_h2(p[8 * HH + 8], p[8 * HH + 9]);
    ((uint4*)A_half)[idx] = o;
}

__global__ void __launch_bounds__(256)
pack_W_kernel(const float* __restrict__ src)
{
    int idx  = blockIdx.x * 256 + threadIdx.x;
    int tile = idx >> 8;
    int v    = idx & 255;
    int ntile = tile >> 6, kt = tile & 63;
    int pair = v >> 5, lane = v & 31;
    int grp = lane >> 2, tg = lane & 3;
    int ne = ntile * 128 + pair * 16 + grp;
    int no = ne + 8;
    int c0 = kt * 16 + tg * 2;
    uint4 o = make_uint4(0u, 0u, 0u, 0u);
    if (ne < VV) {
        const float* pe = src + (size_t)ne * HH + c0;
        o.x = pack_h2(pe[0], pe[1]);
        o.y = pack_h2(pe[8], pe[9]);
    }
    if (no < VV) {
        const float* po = src + (size_t)no * HH + c0;
        o.z = pack_h2(po[0], po[1]);
        o.w = pack_h2(po[8], po[9]);
    }
    ((uint4*)W_half)[idx] = o;
}

// ---------------- GEMM + fused lse partials ----------------
__global__ void __launch_bounds__(NTHREADS, 2)
gemm_f16_kernel(float* __restrict__ C)
{
    extern __shared__ char smem[];
    __shared__ float sbm[2][128], sbs[2][128];   // [warpN][local row]

    const int bm = blockIdx.x;     // M tile (fast dim -> A stays L2 hot)
    const int bn = blockIdx.y;     // N tile
    const int tid = threadIdx.x;
    const int lane = tid & 31;
    const int warp = tid >> 5;
    const int warpM = warp >> 1;   // 0..1 -> 64 rows
    const int warpN = warp & 1;    // 0..1 -> 64 cols
    const int grp = lane >> 2, tg = lane & 3;

    const char* Abase = (const char*)A_half + (size_t)bm * 64 * A_U;
    const char* Bbase = (const char*)W_half + (size_t)bn * 64 * B_U;

    float acc[4][8][4];
    #pragma unroll
    for (int i = 0; i < 4; i++)
        #pragma unroll
        for (int j = 0; j < 8; j++)
            #pragma unroll
            for (int k = 0; k < 4; k++) acc[i][j][k] = 0.f;

    auto load_stage = [&](int kt) {
        char* stg = smem + (kt % NST) * ST;
        const char* asrc = Abase + (size_t)kt * A_U;
        const char* bsrc = Bbase + (size_t)kt * B_U;
        #pragma unroll
        for (int i = 0; i < 2; i++) {
            int j = tid + i * NTHREADS;            // 0..255
            cp16(stg + j * 16, asrc + j * 16);
        }
        #pragma unroll
        for (int i = 0; i < 2; i++) {
            int j = tid + i * NTHREADS;
            cp16(stg + A_U + j * 16, bsrc + j * 16);
        }
        asm volatile("cp.async.commit_group;");
    };

    uint4 afr[2][4], bfr[2][4];
    auto load_frags = [&](int kt, int set) {
        const char* stg = smem + (kt % NST) * ST;
        const char* sA = stg + (size_t)(warpM * 4) * 512 + lane * 16;
        const char* sB = stg + A_U + (size_t)(warpN * 4) * 512 + lane * 16;
        #pragma unroll
        for (int mt = 0; mt < 4; mt++)
            afr[set][mt] = *(const uint4*)(sA + mt * 512);
        #pragma unroll
        for (int pp = 0; pp < 4; pp++)
            bfr[set][pp] = *(const uint4*)(sB + pp * 512);
    };

    // prologue: commit stages 0..4; stage 0 -> fragment set 0
    #pragma unroll
    for (int s = 0; s < NST - 1; s++) load_stage(s);
    asm volatile("cp.async.wait_group 4;");
    __syncthreads();
    load_frags(0, 0);

    #pragma unroll 1
    for (int kt = 0; kt < NK; kt++) {
        const int cur = kt & 1;
        if (kt + NST - 1 < NK) load_stage(kt + NST - 1);  // slot (kt-1)%NST, readers done
        if (kt + 1 < NK) {
            if (kt <= NK - NST)       asm volatile("cp.async.wait_group 4;");
            else if (kt == NK - 5)    asm volatile("cp.async.wait_group 3;");
            else if (kt == NK - 4)    asm volatile("cp.async.wait_group 2;");
            else if (kt == NK - 3)    asm volatile("cp.async.wait_group 1;");
            else                      asm volatile("cp.async.wait_group 0;");
            __syncthreads();           // stage kt+1 globally visible
            load_frags(kt + 1, cur ^ 1);   // LDS overlaps with HMMAs below
        }
        #pragma unroll
        for (int mt = 0; mt < 4; mt++)
            #pragma unroll
            for (int nt = 0; nt < 8; nt++) {
                unsigned b0 = (nt & 1) ? bfr[cur][nt >> 1].z : bfr[cur][nt >> 1].x;
                unsigned b1 = (nt & 1) ? bfr[cur][nt >> 1].w : bfr[cur][nt >> 1].y;
                mma_f16(acc[mt][nt], afr[cur][mt].x, afr[cur][mt].y,
                        afr[cur][mt].z, afr[cur][mt].w, b0, b1);
            }
    }

    // ---- epilogue: C store + per-thread lse over own cols ----
    float lm[4][2], ls[4][2];
    #pragma unroll
    for (int mt = 0; mt < 4; mt++)
        #pragma unroll
        for (int sub = 0; sub < 2; sub++) { lm[mt][sub] = -CUDART_INF_F; ls[mt][sub] = 0.f; }

    #pragma unroll
    for (int mt = 0; mt < 4; mt++) {
        const int r0 = bm * TM + warpM * 64 + mt * 16 + grp;
        #pragma unroll
        for (int nt = 0; nt < 8; nt++) {
            const int c0 = bn * TN + warpN * 64 + nt * 8 + tg * 2;
            if (c0 < VV) {
                size_t base  = (size_t)r0 * VV + c0;
                size_t base2 = base + (size_t)8 * VV;
                C[base]  = acc[mt][nt][0];
                C[base2] = acc[mt][nt][2];
                if (c0 + 1 < VV) {
                    C[base + 1]  = acc[mt][nt][1];
                    C[base2 + 1] = acc[mt][nt][3];
                }
            }
            #pragma unroll
            for (int sub = 0; sub < 2; sub++) {
                #pragma unroll
                for (int cp = 0; cp < 2; cp++) {
                    if (c0 + cp < VV) {
                        float x = acc[mt][nt][sub * 2 + cp];
                        float& m = lm[mt][sub];
                        float& s = ls[mt][sub];
                        if (x > m) { s = s * __expf(m - x) + 1.f; m = x; }
                        else       { s += __expf(x - m); }
                    }
                }
            }
        }
    }
    // quad combine (lanes sharing grp, tg=0..3)
    #pragma unroll
    for (int mt = 0; mt < 4; mt++)
        #pragma unroll
        for (int sub = 0; sub < 2; sub++) {
            #pragma unroll
            for (int off = 1; off <= 2; off <<= 1) {
                float mo = __shfl_xor_sync(0xffffffffu, lm[mt][sub], off);
                float so = __shfl_xor_sync(0xffffffffu, ls[mt][sub], off);
                lse_comb(lm[mt][sub], ls[mt][sub], mo, so);
            }
        }
    if (tg == 0) {
        #pragma unroll
        for (int mt = 0; mt < 4; mt++)
            #pragma unroll
            for (int sub = 0; sub < 2; sub++) {
                int rl = warpM * 64 + mt * 16 + sub * 8 + grp;
                sbm[warpN][rl] = lm[mt][sub];
                sbs[warpN][rl] = ls[mt][sub];
            }
    }
    __syncthreads();
    // one thread per local row: combine the two warpN halves, write partials
    {
        float m = sbm[0][tid], s = sbs[0][tid];
        lse_comb(m, s, sbm[1][tid], sbs[1][tid]);
        size_t idx = (size_t)(bm * TM + tid) * NT + bn;
        part_m[idx] = m;
        part_s[idx] = s;
    }
}

// ---------------- loss from partials ----------------
__global__ void __launch_bounds__(128)
loss_partial_kernel(const float* __restrict__ C, const int* __restrict__ labels)
{
    const int r = blockIdx.x;               // 0..4093 shifted rows
    const int b = r / (TT - 1);
    const int t = r - b * (TT - 1);
    const int row = b * TT + t;

    float m = -CUDART_INF_F, s = 0.f;
    for (int j = threadIdx.x; j < NT; j += 128)
        lse_comb(m, s, part_m[(size_t)row * NT + j], part_s[(size_t)row * NT + j]);

    #pragma unroll
    for (int o = 16; o; o >>= 1) {
        float mo = __shfl_down_sync(0xffffffffu, m, o);
        float so = __shfl_down_sync(0xffffffffu, s, o);
        lse_comb(m, s, mo, so);
    }
    __shared__ float sm_[4], ss_[4];
    const int lane = threadIdx.x & 31, w = threadIdx.x >> 5;
    if (lane == 0) { sm_[w] = m; ss_[w] = s; }
    __syncthreads();
    if (threadIdx.x == 0) {
        m = sm_[0]; s = ss_[0];
        lse_comb(m, s, sm_[1], ss_[1]);
        lse_comb(m, s, sm_[2], ss_[2]);
        lse_comb(m, s, sm_[3], ss_[3]);
        int lbl = labels[row + 1];
        if (lbl < 0) lbl = 0;
        if (lbl >= VV) lbl = VV - 1;
        g_nll[r] = m + __logf(s) - C[(size_t)row * VV + lbl];
    }
}

__global__ void __launch_bounds__(256)
loss_reduce_kernel(float* __restrict__ out_loss)
{
    __shared__ float sh[256];
    float v = 0.f;
    for (int i = threadIdx.x; i < BB * (TT - 1); i += 256) v += g_nll[i];
    sh[threadIdx.x] = v;
    __syncthreads();
    for (int st = 128; st; st >>= 1) {
        if (threadIdx.x < st) sh[threadIdx.x] += sh[threadIdx.x + st];
        __syncthreads();
    }
    if (threadIdx.x == 0) *out_loss = sh[0] / (float)(BB * (TT - 1));
}

// ---------------- launch ----------------
extern "C" void kernel_launch(void* const* d_in, const int* in_sizes, int n_in,
                              void* d_out, int out_size)
{
    const float* hidden = nullptr;
    const float* weight = nullptr;
    const int*   labels = nullptr;
    for (int i = 0; i < n_in; i++) {
        if      (in_sizes[i] == MTOT * HH) hidden = (const float*)d_in[i];
        else if (in_sizes[i] == VV * HH)   weight = (const float*)d_in[i];
        else if (in_sizes[i] == BB * TT)   labels = (const int*)d_in[i];
    }
    float* out = (float*)d_out;

    cudaFuncSetAttribute(gemm_f16_kernel,
                         cudaFuncAttributeMaxDynamicSharedMemorySize, SMEM_TOTAL);

    pack_A_kernel<<<(32 * 64 * 256) / 256, 256>>>(hidden);
    pack_W_kernel<<<(NT * 64 * 256) / 256, 256>>>(weight);

    dim3 grid(MTOT / TM, NT);          // (32, 393)
    gemm_f16_kernel<<<grid, NTHREADS, SMEM_TOTAL>>>(out);

    loss_partial_kernel<<<BB * (TT - 1), 128>>>(out, labels);
    loss_reduce_kernel<<<1, 256>>>(out + (size_t)out_size - 1);
}

// round 14
// speedup vs baseline: 1.3371x; 1.3371x over previous
#include <cuda_runtime.h>
#include <cuda_fp16.h>
#include <math_constants.h>
#include <cstdint>
#include <cstddef>

// ---------------- Problem constants ----------------
#define BB 2
#define TT 2048
#define HH 1024
#define VV 50257
#define MTOT (BB*TT)          // 4096
#define NT 393                // ceil(50257/128) N tiles

// ---------------- GEMM tiling (fp16, 256 thr, 8 warps m64n32) ----------------
#define TM 128
#define TN 128
#define NST 4                 // pipeline stages (TK=16 each)
#define NK 64                 // K iterations
#define NTHREADS 256          // 8 warps: warpM 0..1 (64 rows), warpN 0..3 (32 cols)

#define A_U 4096              // A bytes per kt16 stage (128x16 fp16)
#define B_U 4096              // B bytes per kt16 stage (128x16 fp16)
#define ST  (A_U+B_U)         // 8192
#define SMEM_TOTAL (NST*ST)   // 32768 dynamic

// ---------------- device scratch ----------------
// A_half: [mtile 0..31][kt 0..63] tiles of 4KB; unit16B u = block(0..7)*32+lane:
//   {A[r0][c0],A[r0][c0+1]}, {A[r0+8][c0],A[r0+8][c0+1]},
//   {A[r0][c0+8],A[r0][c0+9]}, {A[r0+8][c0+8],A[r0+8][c0+9]}
//   r0 = mtile*128+block*16+(lane>>2), c0 = kt*16+(lane&3)*2
__device__ __half A_half[MTOT*HH];                     // 8 MB
// W_half: [ntile 0..392][kt 0..63] tiles of 4KB; unit16B u = pair(0..7)*32+lane:
//   ne = ntile*128+pair*16+(lane>>2), no = ne+8, c0 = kt*16+(lane&3)*2
//   {W[ne][c0..c0+1]}, {W[ne][c0+8..c0+9]}, {W[no][c0..c0+1]}, {W[no][c0+8..c0+9]}
__device__ __half W_half[(size_t)NT*131072];           // ~103 MB
__device__ float g_nll[BB*(TT-1)];
__device__ float part_m[(size_t)MTOT*NT];
__device__ float part_s[(size_t)MTOT*NT];

// ---------------- helpers ----------------
__device__ __forceinline__ unsigned pack_h2(float lo, float hi) {
    __half2 h = __floats2half2_rn(lo, hi);
    return *reinterpret_cast<unsigned*>(&h);
}
__device__ __forceinline__ void mma_f16(float* c,
    unsigned a0, unsigned a1, unsigned a2, unsigned a3,
    unsigned b0, unsigned b1)
{
    asm volatile("mma.sync.aligned.m16n8k16.row.col.f32.f16.f16.f32 "
        "{%0,%1,%2,%3}, {%4,%5,%6,%7}, {%8,%9}, {%0,%1,%2,%3};"
        : "+f"(c[0]), "+f"(c[1]), "+f"(c[2]), "+f"(c[3])
        : "r"(a0), "r"(a1), "r"(a2), "r"(a3), "r"(b0), "r"(b1));
}
__device__ __forceinline__ void cp16(void* dst, const void* src) {
    unsigned s = (unsigned)__cvta_generic_to_shared(dst);
    asm volatile("cp.async.cg.shared.global [%0], [%1], 16;" :: "r"(s), "l"(src));
}
// -inf-safe (m, s) logsumexp-state combine; fixed order -> deterministic
__device__ __forceinline__ void lse_comb(float& m, float& s, float mo, float so) {
    float M = fmaxf(m, mo);
    if (M == -CUDART_INF_F) { m = M; s = 0.f; return; }
    s = s * __expf(m - M) + so * __expf(mo - M);
    m = M;
}

// ---------------- pack kernels ----------------
__global__ void __launch_bounds__(256)
pack_A_kernel(const float* __restrict__ src)
{
    int idx  = blockIdx.x * 256 + threadIdx.x;     // 16B unit id
    int tile = idx >> 8;                            // 256 units per kt16 tile
    int v    = idx & 255;
    int mtile = tile >> 6, kt = tile & 63;
    int block = v >> 5, lane = v & 31;
    int grp = lane >> 2, tg = lane & 3;
    int r0 = mtile * 128 + block * 16 + grp;
    int c0 = kt * 16 + tg * 2;
    const float* p = src + (size_t)r0 * HH + c0;
    uint4 o;
    o.x = pack_h2(p[0],          p[1]);
    o.y = pack_h2(p[8 * HH],     p[8 * HH + 1]);
    o.z = pack_h2(p[8],          p[9]);
    o.w = pack_h2(p[8 * HH + 8], p[8 * HH + 9]);
    ((uint4*)A_half)[idx] = o;
}

__global__ void __launch_bounds__(256)
pack_W_kernel(const float* __restrict__ src)
{
    int idx  = blockIdx.x * 256 + threadIdx.x;
    int tile = idx >> 8;
    int v    = idx & 255;
    int ntile = tile >> 6, kt = tile & 63;
    int pair = v >> 5, lane = v & 31;
    int grp = lane >> 2, tg = lane & 3;
    int ne = ntile * 128 + pair * 16 + grp;
    int no = ne + 8;
    int c0 = kt * 16 + tg * 2;
    uint4 o = make_uint4(0u, 0u, 0u, 0u);
    if (ne < VV) {
        const float* pe = src + (size_t)ne * HH + c0;
        o.x = pack_h2(pe[0], pe[1]);
        o.y = pack_h2(pe[8], pe[9]);
    }
    if (no < VV) {
        const float* po = src + (size_t)no * HH + c0;
        o.z = pack_h2(po[0], po[1]);
        o.w = pack_h2(po[8], po[9]);
    }
    ((uint4*)W_half)[idx] = o;
}

// ---------------- GEMM + fused lse partials ----------------
__global__ void __launch_bounds__(NTHREADS, 2)
gemm_f16_kernel(float* __restrict__ C)
{
    extern __shared__ char smem[];
    __shared__ float sbm[4][128], sbs[4][128];   // [warpN][local row]

    const int bm = blockIdx.x;     // M tile (fast dim -> A stays L2 hot)
    const int bn = blockIdx.y;     // N tile
    const int tid = threadIdx.x;
    const int lane = tid & 31;
    const int warp = tid >> 5;
    const int warpM = warp >> 2;   // 0..1 -> 64 rows
    const int warpN = warp & 3;    // 0..3 -> 32 cols
    const int grp = lane >> 2, tg = lane & 3;

    const char* Abase = (const char*)A_half + (size_t)bm * 64 * A_U;
    const char* Bbase = (const char*)W_half + (size_t)bn * 64 * B_U;

    float acc[4][4][4];
    #pragma unroll
    for (int i = 0; i < 4; i++)
        #pragma unroll
        for (int j = 0; j < 4; j++)
            #pragma unroll
            for (int k = 0; k < 4; k++) acc[i][j][k] = 0.f;

    // Stage: [A 4KB = 256 units][B 4KB = 256 units]; 2 units per thread.
    auto load_stage = [&](int kt) {
        char* stg = smem + (kt & (NST - 1)) * ST;
        const char* asrc = Abase + (size_t)kt * A_U;
        const char* bsrc = Bbase + (size_t)kt * B_U;
        cp16(stg + tid * 16,       asrc + tid * 16);
        cp16(stg + A_U + tid * 16, bsrc + tid * 16);
        asm volatile("cp.async.commit_group;");
    };

    load_stage(0); load_stage(1); load_stage(2);

    #pragma unroll 1
    for (int kt = 0; kt < NK; kt++) {
        if (kt < NK - 2)        asm volatile("cp.async.wait_group 2;");
        else if (kt == NK - 2)  asm volatile("cp.async.wait_group 1;");
        else                    asm volatile("cp.async.wait_group 0;");
        __syncthreads();   // stage kt visible; stage (kt-1) reads finished

        if (kt + 3 < NK) load_stage(kt + 3);   // into the slot freed last iter

        const char* stg = smem + (kt & (NST - 1)) * ST;
        const char* sA = stg + (size_t)(warpM * 4) * 512 + lane * 16;
        const char* sB = stg + A_U + (size_t)(warpN * 2) * 512 + lane * 16;

        uint4 af[4], bf[2];
        #pragma unroll
        for (int mt = 0; mt < 4; mt++)
            af[mt] = *(const uint4*)(sA + mt * 512);
        #pragma unroll
        for (int pp = 0; pp < 2; pp++)
            bf[pp] = *(const uint4*)(sB + pp * 512);

        #pragma unroll
        for (int mt = 0; mt < 4; mt++)
            #pragma unroll
            for (int nt = 0; nt < 4; nt++) {
                unsigned b0 = (nt & 1) ? bf[nt >> 1].z : bf[nt >> 1].x;
                unsigned b1 = (nt & 1) ? bf[nt >> 1].w : bf[nt >> 1].y;
                mma_f16(acc[mt][nt], af[mt].x, af[mt].y, af[mt].z, af[mt].w, b0, b1);
            }
    }

    // ---- epilogue: C store + per-thread lse over own cols ----
    float lm[4][2], ls[4][2];
    #pragma unroll
    for (int mt = 0; mt < 4; mt++)
        #pragma unroll
        for (int sub = 0; sub < 2; sub++) { lm[mt][sub] = -CUDART_INF_F; ls[mt][sub] = 0.f; }

    #pragma unroll
    for (int mt = 0; mt < 4; mt++) {
        const int r0 = bm * TM + warpM * 64 + mt * 16 + grp;
        #pragma unroll
        for (int nt = 0; nt < 4; nt++) {
            const int c0 = bn * TN + warpN * 32 + nt * 8 + tg * 2;
            if (c0 < VV) {
                size_t base  = (size_t)r0 * VV + c0;
                size_t base2 = base + (size_t)8 * VV;
                C[base]  = acc[mt][nt][0];
                C[base2] = acc[mt][nt][2];
                if (c0 + 1 < VV) {
                    C[base + 1]  = acc[mt][nt][1];
                    C[base2 + 1] = acc[mt][nt][3];
                }
            }
            #pragma unroll
            for (int sub = 0; sub < 2; sub++) {
                #pragma unroll
                for (int cp = 0; cp < 2; cp++) {
                    if (c0 + cp < VV) {
                        float x = acc[mt][nt][sub * 2 + cp];
                        float& m = lm[mt][sub];
                        float& s = ls[mt][sub];
                        if (x > m) { s = s * __expf(m - x) + 1.f; m = x; }
                        else       { s += __expf(x - m); }
                    }
                }
            }
        }
    }
    // quad combine (lanes sharing grp, tg=0..3)
    #pragma unroll
    for (int mt = 0; mt < 4; mt++)
        #pragma unroll
        for (int sub = 0; sub < 2; sub++) {
            #pragma unroll
            for (int off = 1; off <= 2; off <<= 1) {
                float mo = __shfl_xor_sync(0xffffffffu, lm[mt][sub], off);
                float so = __shfl_xor_sync(0xffffffffu, ls[mt][sub], off);
                lse_comb(lm[mt][sub], ls[mt][sub], mo, so);
            }
        }
    if (tg == 0) {
        #pragma unroll
        for (int mt = 0; mt < 4; mt++)
            #pragma unroll
            for (int sub = 0; sub < 2; sub++) {
                int rl = warpM * 64 + mt * 16 + sub * 8 + grp;
                sbm[warpN][rl] = lm[mt][sub];
                sbs[warpN][rl] = ls[mt][sub];
            }
    }
    __syncthreads();
    // threads 0..127: combine the four warpN quarters (fixed order), write partials
    if (tid < 128) {
        float m = sbm[0][tid], s = sbs[0][tid];
        lse_comb(m, s, sbm[1][tid], sbs[1][tid]);
        lse_comb(m, s, sbm[2][tid], sbs[2][tid]);
        lse_comb(m, s, sbm[3][tid], sbs[3][tid]);
        size_t idx = (size_t)(bm * TM + tid) * NT + bn;
        part_m[idx] = m;
        part_s[idx] = s;
    }
}

// ---------------- loss from partials ----------------
__global__ void __launch_bounds__(128)
loss_partial_kernel(const float* __restrict__ C, const int* __restrict__ labels)
{
    const int r = blockIdx.x;               // 0..4093 shifted rows
    const int b = r / (TT - 1);
    const int t = r - b * (TT - 1);
    const int row = b * TT + t;

    float m = -CUDART_INF_F, s = 0.f;
    for (int j = threadIdx.x; j < NT; j += 128)
        lse_comb(m, s, part_m[(size_t)row * NT + j], part_s[(size_t)row * NT + j]);

    #pragma unroll
    for (int o = 16; o; o >>= 1) {
        float mo = __shfl_down_sync(0xffffffffu, m, o);
        float so = __shfl_down_sync(0xffffffffu, s, o);
        lse_comb(m, s, mo, so);
    }
    __shared__ float sm_[4], ss_[4];
    const int lane = threadIdx.x & 31, w = threadIdx.x >> 5;
    if (lane == 0) { sm_[w] = m; ss_[w] = s; }
    __syncthreads();
    if (threadIdx.x == 0) {
        m = sm_[0]; s = ss_[0];
        lse_comb(m, s, sm_[1], ss_[1]);
        lse_comb(m, s, sm_[2], ss_[2]);
        lse_comb(m, s, sm_[3], ss_[3]);
        int lbl = labels[row + 1];
        if (lbl < 0) lbl = 0;
        if (lbl >= VV) lbl = VV - 1;
        g_nll[r] = m + __logf(s) - C[(size_t)row * VV + lbl];
    }
}

__global__ void __launch_bounds__(256)
loss_reduce_kernel(float* __restrict__ out_loss)
{
    __shared__ float sh[256];
    float v = 0.f;
    for (int i = threadIdx.x; i < BB * (TT - 1); i += 256) v += g_nll[i];
    sh[threadIdx.x] = v;
    __syncthreads();
    for (int st = 128; st; st >>= 1) {
        if (threadIdx.x < st) sh[threadIdx.x] += sh[threadIdx.x + st];
        __syncthreads();
    }
    if (threadIdx.x == 0) *out_loss = sh[0] / (float)(BB * (TT - 1));
}

// ---------------- launch ----------------
extern "C" void kernel_launch(void* const* d_in, const int* in_sizes, int n_in,
                              void* d_out, int out_size)
{
    const float* hidden = nullptr;
    const float* weight = nullptr;
    const int*   labels = nullptr;
    for (int i = 0; i < n_in; i++) {
        if      (in_sizes[i] == MTOT * HH) hidden = (const float*)d_in[i];
        else if (in_sizes[i] == VV * HH)   weight = (const float*)d_in[i];
        else if (in_sizes[i] == BB * TT)   labels = (const int*)d_in[i];
    }
    float* out = (float*)d_out;

    cudaFuncSetAttribute(gemm_f16_kernel,
                         cudaFuncAttributeMaxDynamicSharedMemorySize, SMEM_TOTAL);

    pack_A_kernel<<<(32 * 64 * 256) / 256, 256>>>(hidden);
    pack_W_kernel<<<(NT * 64 * 256) / 256, 256>>>(weight);

    dim3 grid(MTOT / TM, NT);          // (32, 393)
    gemm_f16_kernel<<<grid, NTHREADS, SMEM_TOTAL>>>(out);

    loss_partial_kernel<<<BB * (TT - 1), 128>>>(out, labels);
    loss_reduce_kernel<<<1, 256>>>(out + (size_t)out_size - 1);
}

// round 15
// speedup vs baseline: 2.3873x; 1.7854x over previous
#include <cuda_runtime.h>
#include <cuda_fp16.h>
#include <math_constants.h>
#include <cstdint>
#include <cstddef>

// ---------------- Problem constants ----------------
#define BB 2
#define TT 2048
#define HH 1024
#define VV 50257
#define MTOT (BB*TT)          // 4096
#define NT 393                // ceil(50257/128) N tiles

// ---------------- GEMM tiling (fp16, 128 thr, 4 warps m64n64, frag dbuf) ----------------
#define TM 128
#define TN 128
#define NST 8                 // pipeline stages (TK=16 each)
#define NK 64                 // K iterations
#define NTHREADS 128

#define A_U 4096              // A bytes per kt16 stage (128x16 fp16)
#define B_U 4096              // B bytes per kt16 stage (128x16 fp16)
#define ST  (A_U+B_U)         // 8192
#define SMEM_TOTAL (NST*ST)   // 65536 dynamic

// ---------------- device scratch ----------------
// A_half: [mtile 0..31][kt 0..63] tiles of 4KB; unit16B u = block(0..7)*32+lane:
//   {A[r0][c0],A[r0][c0+1]}, {A[r0+8][c0],A[r0+8][c0+1]},
//   {A[r0][c0+8],A[r0][c0+9]}, {A[r0+8][c0+8],A[r0+8][c0+9]}
//   r0 = mtile*128+block*16+(lane>>2), c0 = kt*16+(lane&3)*2
__device__ __half A_half[MTOT*HH];                     // 8 MB
// W_half: [ntile 0..392][kt 0..63] tiles of 4KB; unit16B u = pair(0..7)*32+lane:
//   ne = ntile*128+pair*16+(lane>>2), no = ne+8, c0 = kt*16+(lane&3)*2
//   {W[ne][c0..c0+1]}, {W[ne][c0+8..c0+9]}, {W[no][c0..c0+1]}, {W[no][c0+8..c0+9]}
__device__ __half W_half[(size_t)NT*131072];           // ~103 MB
__device__ float g_nll[BB*(TT-1)];
__device__ float part_m[(size_t)MTOT*NT];
__device__ float part_s[(size_t)MTOT*NT];

// ---------------- helpers ----------------
__device__ __forceinline__ unsigned pack_h2(float lo, float hi) {
    __half2 h = __floats2half2_rn(lo, hi);
    return *reinterpret_cast<unsigned*>(&h);
}
__device__ __forceinline__ void mma_f16(float* c,
    unsigned a0, unsigned a1, unsigned a2, unsigned a3,
    unsigned b0, unsigned b1)
{
    asm volatile("mma.sync.aligned.m16n8k16.row.col.f32.f16.f16.f32 "
        "{%0,%1,%2,%3}, {%4,%5,%6,%7}, {%8,%9}, {%0,%1,%2,%3};"
        : "+f"(c[0]), "+f"(c[1]), "+f"(c[2]), "+f"(c[3])
        : "r"(a0), "r"(a1), "r"(a2), "r"(a3), "r"(b0), "r"(b1));
}
__device__ __forceinline__ void cp16(void* dst, const void* src) {
    unsigned s = (unsigned)__cvta_generic_to_shared(dst);
    asm volatile("cp.async.cg.shared.global [%0], [%1], 16;" :: "r"(s), "l"(src));
}
// -inf-safe (m, s) logsumexp-state combine; fixed order -> deterministic
__device__ __forceinline__ void lse_comb(float& m, float& s, float mo, float so) {
    float M = fmaxf(m, mo);
    if (M == -CUDART_INF_F) { m = M; s = 0.f; return; }
    s = s * __expf(m - M) + so * __expf(mo - M);
    m = M;
}

// ---------------- pack kernels ----------------
__global__ void __launch_bounds__(256)
pack_A_kernel(const float* __restrict__ src)
{
    int idx  = blockIdx.x * 256 + threadIdx.x;     // 16B unit id
    int tile = idx >> 8;                            // 256 units per kt16 tile
    int v    = idx & 255;
    int mtile = tile >> 6, kt = tile & 63;
    int block = v >> 5, lane = v & 31;
    int grp = lane >> 2, tg = lane & 3;
    int r0 = mtile * 128 + block * 16 + grp;
    int c0 = kt * 16 + tg * 2;
    const float* p = src + (size_t)r0 * HH + c0;
    uint4 o;
    o.x = pack_h2(p[0],          p[1]);
    o.y = pack_h2(p[8 * HH],     p[8 * HH + 1]);
    o.z = pack_h2(p[8],          p[9]);
    o.w = pack_h2(p[8 * HH + 8], p[8 * HH + 9]);
    ((uint4*)A_half)[idx] = o;
}

__global__ void __launch_bounds__(256)
pack_W_kernel(const float* __restrict__ src)
{
    int idx  = blockIdx.x * 256 + threadIdx.x;
    int tile = idx >> 8;
    int v    = idx & 255;
    int ntile = tile >> 6, kt = tile & 63;
    int pair = v >> 5, lane = v & 31;
    int grp = lane >> 2, tg = lane & 3;
    int ne = ntile * 128 + pair * 16 + grp;
    int no = ne + 8;
    int c0 = kt * 16 + tg * 2;
    uint4 o = make_uint4(0u, 0u, 0u, 0u);
    if (ne < VV) {
        const float* pe = src + (size_t)ne * HH + c0;
        o.x = pack_h2(pe[0], pe[1]);
        o.y = pack_h2(pe[8], pe[9]);
    }
    if (no < VV) {
        const float* po = src + (size_t)no * HH + c0;
        o.z = pack_h2(po[0], po[1]);
        o.w = pack_h2(po[8], po[9]);
    }
    ((uint4*)W_half)[idx] = o;
}

// ---------------- GEMM + fused lse partials ----------------
// LOAD_FRAGS / HMMA_SET use named arrays with constant indices only -> registers.
#define LOAD_FRAGS(kt, af, bf) do {                                             \
    const char* stg_ = smem + ((kt) & (NST - 1)) * ST;                          \
    const char* sA_ = stg_ + (size_t)(warpM * 4) * 512 + lane * 16;             \
    const char* sB_ = stg_ + A_U + (size_t)(warpN * 4) * 512 + lane * 16;       \
    af[0] = *(const uint4*)(sA_);            af[1] = *(const uint4*)(sA_ + 512);\
    af[2] = *(const uint4*)(sA_ + 1024);     af[3] = *(const uint4*)(sA_ + 1536);\
    bf[0] = *(const uint4*)(sB_);            bf[1] = *(const uint4*)(sB_ + 512);\
    bf[2] = *(const uint4*)(sB_ + 1024);     bf[3] = *(const uint4*)(sB_ + 1536);\
} while (0)

#define HMMA_SET(af, bf) do {                                                   \
    _Pragma("unroll")                                                           \
    for (int mt = 0; mt < 4; mt++) {                                            \
        _Pragma("unroll")                                                       \
        for (int nt = 0; nt < 8; nt++) {                                        \
            unsigned b0_ = (nt & 1) ? bf[nt >> 1].z : bf[nt >> 1].x;            \
            unsigned b1_ = (nt & 1) ? bf[nt >> 1].w : bf[nt >> 1].y;            \
            mma_f16(acc[mt][nt], af[mt].x, af[mt].y, af[mt].z, af[mt].w, b0_, b1_);\
        }                                                                       \
    }                                                                           \
} while (0)

__global__ void __launch_bounds__(NTHREADS, 2)
gemm_f16_kernel(float* __restrict__ C)
{
    extern __shared__ char smem[];
    __shared__ float sbm[2][128], sbs[2][128];   // [warpN][local row]

    const int bm = blockIdx.x;     // M tile (fast dim -> A stays L2 hot)
    const int bn = blockIdx.y;     // N tile
    const int tid = threadIdx.x;
    const int lane = tid & 31;
    const int warp = tid >> 5;
    const int warpM = warp >> 1;   // 0..1 -> 64 rows
    const int warpN = warp & 1;    // 0..1 -> 64 cols
    const int grp = lane >> 2, tg = lane & 3;

    const char* Abase = (const char*)A_half + (size_t)bm * 64 * A_U;
    const char* Bbase = (const char*)W_half + (size_t)bn * 64 * B_U;

    float acc[4][8][4];
    #pragma unroll
    for (int i = 0; i < 4; i++)
        #pragma unroll
        for (int j = 0; j < 8; j++)
            #pragma unroll
            for (int k = 0; k < 4; k++) acc[i][j][k] = 0.f;

    auto load_stage = [&](int kt) {
        char* stg = smem + (kt & (NST - 1)) * ST;
        const char* asrc = Abase + (size_t)kt * A_U;
        const char* bsrc = Bbase + (size_t)kt * B_U;
        #pragma unroll
        for (int i = 0; i < 2; i++) {
            int j = tid + i * NTHREADS;            // 0..255
            cp16(stg + j * 16, asrc + j * 16);
        }
        #pragma unroll
        for (int i = 0; i < 2; i++) {
            int j = tid + i * NTHREADS;
            cp16(stg + A_U + j * 16, bsrc + j * 16);
        }
        asm volatile("cp.async.commit_group;");
    };

    uint4 af0[4], bf0[4], af1[4], bf1[4];

    // prologue: commit stages 0..6; stage 0 -> set0
    #pragma unroll
    for (int s = 0; s < NST - 1; s++) load_stage(s);
    asm volatile("cp.async.wait_group 6;");
    __syncthreads();
    LOAD_FRAGS(0, af0, bf0);

    // main: kt = 0..55 in pairs; frag set for kt+1 loaded under HMMAs of kt
    #pragma unroll 1
    for (int kt2 = 0; kt2 < 28; kt2++) {
        const int kt = 2 * kt2;
        load_stage(kt + 7);                        // slot (kt-1)%8: readers done pre-barrier
        asm volatile("cp.async.wait_group 6;");    // stage kt+1 complete
        __syncthreads();
        LOAD_FRAGS(kt + 1, af1, bf1);              // overlaps HMMAs below
        HMMA_SET(af0, bf0);
        load_stage(kt + 8);                        // slot kt%8: reads done pre-barrier
        asm volatile("cp.async.wait_group 6;");    // stage kt+2 complete
        __syncthreads();
        LOAD_FRAGS(kt + 2, af0, bf0);
        HMMA_SET(af1, bf1);
    }
    // tail: stages 56..62 committed; commit 63, drain, all resident
    load_stage(63);
    asm volatile("cp.async.wait_group 0;");
    __syncthreads();
    #pragma unroll 1
    for (int kt = 56; kt < NK; kt += 2) {
        LOAD_FRAGS(kt + 1, af1, bf1);
        HMMA_SET(af0, bf0);
        if (kt + 2 < NK) LOAD_FRAGS(kt + 2, af0, bf0);
        HMMA_SET(af1, bf1);
    }

    // ---- epilogue: C store + per-thread lse over own cols ----
    float lm[4][2], ls[4][2];
    #pragma unroll
    for (int mt = 0; mt < 4; mt++)
        #pragma unroll
        for (int sub = 0; sub < 2; sub++) { lm[mt][sub] = -CUDART_INF_F; ls[mt][sub] = 0.f; }

    #pragma unroll
    for (int mt = 0; mt < 4; mt++) {
        const int r0 = bm * TM + warpM * 64 + mt * 16 + grp;
        #pragma unroll
        for (int nt = 0; nt < 8; nt++) {
            const int c0 = bn * TN + warpN * 64 + nt * 8 + tg * 2;
            if (c0 < VV) {
                size_t base  = (size_t)r0 * VV + c0;
                size_t base2 = base + (size_t)8 * VV;
                C[base]  = acc[mt][nt][0];
                C[base2] = acc[mt][nt][2];
                if (c0 + 1 < VV) {
                    C[base + 1]  = acc[mt][nt][1];
                    C[base2 + 1] = acc[mt][nt][3];
                }
            }
            #pragma unroll
            for (int sub = 0; sub < 2; sub++) {
                #pragma unroll
                for (int cp = 0; cp < 2; cp++) {
                    if (c0 + cp < VV) {
                        float x = acc[mt][nt][sub * 2 + cp];
                        float& m = lm[mt][sub];
                        float& s = ls[mt][sub];
                        if (x > m) { s = s * __expf(m - x) + 1.f; m = x; }
                        else       { s += __expf(x - m); }
                    }
                }
            }
        }
    }
    // quad combine (lanes sharing grp, tg=0..3)
    #pragma unroll
    for (int mt = 0; mt < 4; mt++)
        #pragma unroll
        for (int sub = 0; sub < 2; sub++) {
            #pragma unroll
            for (int off = 1; off <= 2; off <<= 1) {
                float mo = __shfl_xor_sync(0xffffffffu, lm[mt][sub], off);
                float so = __shfl_xor_sync(0xffffffffu, ls[mt][sub], off);
                lse_comb(lm[mt][sub], ls[mt][sub], mo, so);
            }
        }
    if (tg == 0) {
        #pragma unroll
        for (int mt = 0; mt < 4; mt++)
            #pragma unroll
            for (int sub = 0; sub < 2; sub++) {
                int rl = warpM * 64 + mt * 16 + sub * 8 + grp;
                sbm[warpN][rl] = lm[mt][sub];
                sbs[warpN][rl] = ls[mt][sub];
            }
    }
    __syncthreads();
    // one thread per local row: combine the two warpN halves, write partials
    {
        float m = sbm[0][tid], s = sbs[0][tid];
        lse_comb(m, s, sbm[1][tid], sbs[1][tid]);
        size_t idx = (size_t)(bm * TM + tid) * NT + bn;
        part_m[idx] = m;
        part_s[idx] = s;
    }
}

// ---------------- loss from partials ----------------
__global__ void __launch_bounds__(128)
loss_partial_kernel(const float* __restrict__ C, const int* __restrict__ labels)
{
    const int r = blockIdx.x;               // 0..4093 shifted rows
    const int b = r / (TT - 1);
    const int t = r - b * (TT - 1);
    const int row = b * TT + t;

    float m = -CUDART_INF_F, s = 0.f;
    for (int j = threadIdx.x; j < NT; j += 128)
        lse_comb(m, s, part_m[(size_t)row * NT + j], part_s[(size_t)row * NT + j]);

    #pragma unroll
    for (int o = 16; o; o >>= 1) {
        float mo = __shfl_down_sync(0xffffffffu, m, o);
        float so = __shfl_down_sync(0xffffffffu, s, o);
        lse_comb(m, s, mo, so);
    }
    __shared__ float sm_[4], ss_[4];
    const int lane = threadIdx.x & 31, w = threadIdx.x >> 5;
    if (lane == 0) { sm_[w] = m; ss_[w] = s; }
    __syncthreads();
    if (threadIdx.x == 0) {
        m = sm_[0]; s = ss_[0];
        lse_comb(m, s, sm_[1], ss_[1]);
        lse_comb(m, s, sm_[2], ss_[2]);
        lse_comb(m, s, sm_[3], ss_[3]);
        int lbl = labels[row + 1];
        if (lbl < 0) lbl = 0;
        if (lbl >= VV) lbl = VV - 1;
        g_nll[r] = m + __logf(s) - C[(size_t)row * VV + lbl];
    }
}

__global__ void __launch_bounds__(256)
loss_reduce_kernel(float* __restrict__ out_loss)
{
    __shared__ float sh[256];
    float v = 0.f;
    for (int i = threadIdx.x; i < BB * (TT - 1); i += 256) v += g_nll[i];
    sh[threadIdx.x] = v;
    __syncthreads();
    for (int st = 128; st; st >>= 1) {
        if (threadIdx.x < st) sh[threadIdx.x] += sh[threadIdx.x + st];
        __syncthreads();
    }
    if (threadIdx.x == 0) *out_loss = sh[0] / (float)(BB * (TT - 1));
}

// ---------------- launch ----------------
extern "C" void kernel_launch(void* const* d_in, const int* in_sizes, int n_in,
                              void* d_out, int out_size)
{
    const float* hidden = nullptr;
    const float* weight = nullptr;
    const int*   labels = nullptr;
    for (int i = 0; i < n_in; i++) {
        if      (in_sizes[i] == MTOT * HH) hidden = (const float*)d_in[i];
        else if (in_sizes[i] == VV * HH)   weight = (const float*)d_in[i];
        else if (in_sizes[i] == BB * TT)   labels = (const int*)d_in[i];
    }
    float* out = (float*)d_out;

    cudaFuncSetAttribute(gemm_f16_kernel,
                         cudaFuncAttributeMaxDynamicSharedMemorySize, SMEM_TOTAL);

    pack_A_kernel<<<(32 * 64 * 256) / 256, 256>>>(hidden);
    pack_W_kernel<<<(NT * 64 * 256) / 256, 256>>>(weight);

    dim3 grid(MTOT / TM, NT);          // (32, 393)
    gemm_f16_kernel<<<grid, NTHREADS, SMEM_TOTAL>>>(out);

    loss_partial_kernel<<<BB * (TT - 1), 128>>>(out, labels);
    loss_reduce_kernel<<<1, 256>>>(out + (size_t)out_size - 1);
}